// round 1
// baseline (speedup 1.0000x reference)
#include <cuda_runtime.h>
#include <math_constants.h>

// Problem constants (fixed shapes from reference)
#define N_VEC   65536           // 16*4096 vectors
#define D       64              // embedding dim
#define K       1024            // codebook size
#define TK      128             // codebook tile (smem): 128*64*4 = 32KB
#define NTILE   64              // vectors per block
#define NBLOCKS (N_VEC / NTILE) // 1024

// Output layout in d_out (flattened tuple, reference return order):
//   [0, 4194304)                      quantized_st  (f32)
//   [4194304, 4194304+67108864)       encodings     (f32 one-hot)
//   [71303168, 71303171)              loss, codebook_loss, commitment_loss
#define OUT_E_OFF  ((size_t)N_VEC * D)                 // 4194304
#define OUT_S_OFF  (OUT_E_OFF + (size_t)N_VEC * K)     // 71303168

__device__ float  g_B[K];          // ||e_k||^2 per code
__device__ double g_part[NBLOCKS]; // per-block loss partial sums

// ---------------------------------------------------------------------------
// Kernel 1: precompute ||e_k||^2 (mimics jnp.sum(embedding*embedding, axis=1))
// ---------------------------------------------------------------------------
__global__ void vq_prep_kernel(const float* __restrict__ emb) {
    int k = blockIdx.x * blockDim.x + threadIdx.x;
    if (k < K) {
        float b = 0.f;
        #pragma unroll
        for (int d = 0; d < D; d++) {
            float v = emb[k * D + d];
            b += v * v;
        }
        g_B[k] = b;
    }
}

// ---------------------------------------------------------------------------
// Kernel 2: main VQ — argmin over codebook with reference-rounding mimicry,
// then write quantized_st, one-hot encodings, and per-block loss partials.
// ---------------------------------------------------------------------------
__global__ __launch_bounds__(NTILE) void vq_main_kernel(
    const float* __restrict__ x_g,
    const float* __restrict__ emb,
    float* __restrict__ out)
{
    __shared__ float  sE[TK * D];   // 32KB codebook tile
    __shared__ float  sB[TK];
    __shared__ int    sIdx[NTILE];
    __shared__ double sRed[NTILE];

    const int tid = threadIdx.x;
    const int n0  = blockIdx.x * NTILE;
    const int n   = n0 + tid;

    // Load this thread's vector into registers (16x LDG.128)
    float x[D];
    {
        const float4* xg = reinterpret_cast<const float4*>(x_g + (size_t)n * D);
        #pragma unroll
        for (int j = 0; j < D / 4; j++) {
            float4 v = xg[j];
            x[4*j+0] = v.x; x[4*j+1] = v.y; x[4*j+2] = v.z; x[4*j+3] = v.w;
        }
    }

    // A = sum(x*x) — common across k; 1-ulp differences vs reference are a
    // uniform grid shift of all distances (same binade) => argmin-invariant.
    float A = 0.f;
    #pragma unroll
    for (int d = 0; d < D; d++) A = fmaf(x[d], x[d], A);

    float best = CUDART_INF_F;
    int   bidx = 0;

    for (int k0 = 0; k0 < K; k0 += TK) {
        __syncthreads();
        // Cooperative tile load (coalesced float4)
        {
            const float4* g4 = reinterpret_cast<const float4*>(emb + (size_t)k0 * D);
            float4* s4 = reinterpret_cast<float4*>(sE);
            #pragma unroll
            for (int i = tid; i < TK * D / 4; i += NTILE) s4[i] = g4[i];
            for (int i = tid; i < TK; i += NTILE) sB[i] = g_B[k0 + i];
        }
        __syncthreads();

        // 4 independent FMA chains (4 codes at a time) — broadcast LDS.128
        #pragma unroll 1
        for (int kk = 0; kk < TK; kk += 4) {
            const float4* e0 = reinterpret_cast<const float4*>(sE + (kk + 0) * D);
            const float4* e1 = reinterpret_cast<const float4*>(sE + (kk + 1) * D);
            const float4* e2 = reinterpret_cast<const float4*>(sE + (kk + 2) * D);
            const float4* e3 = reinterpret_cast<const float4*>(sE + (kk + 3) * D);
            float a0 = 0.f, a1 = 0.f, a2 = 0.f, a3 = 0.f;
            #pragma unroll
            for (int j = 0; j < D / 4; j++) {
                float4 v0 = e0[j], v1 = e1[j], v2 = e2[j], v3 = e3[j];
                // strictly ascending-d sequential accumulation per chain
                a0 = fmaf(x[4*j+0], v0.x, a0);
                a0 = fmaf(x[4*j+1], v0.y, a0);
                a0 = fmaf(x[4*j+2], v0.z, a0);
                a0 = fmaf(x[4*j+3], v0.w, a0);
                a1 = fmaf(x[4*j+0], v1.x, a1);
                a1 = fmaf(x[4*j+1], v1.y, a1);
                a1 = fmaf(x[4*j+2], v1.z, a1);
                a1 = fmaf(x[4*j+3], v1.w, a1);
                a2 = fmaf(x[4*j+0], v2.x, a2);
                a2 = fmaf(x[4*j+1], v2.y, a2);
                a2 = fmaf(x[4*j+2], v2.z, a2);
                a2 = fmaf(x[4*j+3], v2.w, a2);
                a3 = fmaf(x[4*j+0], v3.x, a3);
                a3 = fmaf(x[4*j+1], v3.y, a3);
                a3 = fmaf(x[4*j+2], v3.z, a3);
                a3 = fmaf(x[4*j+3], v3.w, a3);
            }
            // dist = fl(fl(A + B_k) - 2*dot)  (2*dot exact: single final rounding,
            // identical to the reference's fl(S) - fl(2C) then fl of the subtract)
            float s0 = A + sB[kk + 0];
            float s1 = A + sB[kk + 1];
            float s2 = A + sB[kk + 2];
            float s3 = A + sB[kk + 3];
            float d0 = s0 - 2.f * a0;
            float d1 = s1 - 2.f * a1;
            float d2 = s2 - 2.f * a2;
            float d3 = s3 - 2.f * a3;
            // ascending k, strict <  => first-occurrence min (jnp.argmin semantics)
            if (d0 < best) { best = d0; bidx = k0 + kk + 0; }
            if (d1 < best) { best = d1; bidx = k0 + kk + 1; }
            if (d2 < best) { best = d2; bidx = k0 + kk + 2; }
            if (d3 < best) { best = d3; bidx = k0 + kk + 3; }
        }
    }

    sIdx[tid] = bidx;
    __syncthreads();

    // quantized_st + loss partials (coalesced; mimic fl(x + fl(q - x)))
    double lsum = 0.0;
    #pragma unroll 1
    for (int i = tid; i < NTILE * D; i += NTILE) {
        int r = i >> 6;          // row within tile (D = 64)
        int d = i & (D - 1);
        int idx = sIdx[r];
        float q  = emb[idx * D + d];
        float xx = x_g[(size_t)(n0 + r) * D + d];
        float diff = q - xx;                 // fl(q - x)
        float qst  = xx + diff;              // fl(x + fl(q - x)) — do NOT fold to q
        out[(size_t)(n0 + r) * D + d] = qst;
        float t = diff * diff;               // fl32 square, then wide accumulate
        lsum += (double)t;
    }
    sRed[tid] = lsum;
    __syncthreads();
    #pragma unroll
    for (int s = NTILE / 2; s > 0; s >>= 1) {
        if (tid < s) sRed[tid] += sRed[tid + s];
        __syncthreads();
    }
    if (tid == 0) g_part[blockIdx.x] = sRed[0];

    // encodings: write the full one-hot rows directly (covers 0xAA poison)
    float* eout = out + OUT_E_OFF;
    #pragma unroll 1
    for (int i = tid; i < NTILE * (K / 4); i += NTILE) {
        int r  = i >> 8;         // K/4 = 256 float4 per row
        int c4 = i & 255;
        int idx = sIdx[r];
        float4 v = make_float4(0.f, 0.f, 0.f, 0.f);
        if ((idx >> 2) == c4) {
            reinterpret_cast<float*>(&v)[idx & 3] = 1.f;
        }
        reinterpret_cast<float4*>(eout + (size_t)(n0 + r) * K)[c4] = v;
    }
}

// ---------------------------------------------------------------------------
// Kernel 3: deterministic final loss reduction + scalar outputs
// ---------------------------------------------------------------------------
__global__ void vq_finalize_kernel(float* __restrict__ out) {
    __shared__ double sR[256];
    int tid = threadIdx.x;
    double s = 0.0;
    for (int i = tid; i < NBLOCKS; i += 256) s += g_part[i];
    sR[tid] = s;
    __syncthreads();
    #pragma unroll
    for (int st = 128; st > 0; st >>= 1) {
        if (tid < st) sR[tid] += sR[tid + st];
        __syncthreads();
    }
    if (tid == 0) {
        float cb = (float)(sR[0] / (double)((size_t)N_VEC * D)); // codebook_loss
        float cm = cb;                                           // commitment_loss (identical forward)
        float loss = cb + 0.25f * cm;
        out[OUT_S_OFF + 0] = loss;
        out[OUT_S_OFF + 1] = cb;
        out[OUT_S_OFF + 2] = cm;
    }
}

// ---------------------------------------------------------------------------
extern "C" void kernel_launch(void* const* d_in, const int* in_sizes, int n_in,
                              void* d_out, int out_size) {
    const float* x   = (const float*)d_in[0];  // inputs [16,4096,64] f32
    const float* emb = (const float*)d_in[1];  // embedding [1024,64] f32
    float* out = (float*)d_out;

    vq_prep_kernel<<<1, K>>>(emb);
    vq_main_kernel<<<NBLOCKS, NTILE>>>(x, emb, out);
    vq_finalize_kernel<<<1, 256>>>(out);
}